// round 9
// baseline (speedup 1.0000x reference)
#include <cuda_runtime.h>

#define NBINS 64
#define NT 128              // threads per block
#define BPI 15              // blocks per image
#define NIMG 48             // 2 tensors * 8 batch * 3 channels
#define IMG_PIX 65536       // 256*256
#define IMG_F4 16384        // float4 elements per image
#define WIN 4               // window half-width (validated ~1e-5)
#define NROW (NBINS + 2*WIN)  // 72 rows: bins -4..67 (guards absorb edges)
#define NBLK (NIMG * BPI)   // 720

// zero at load; finalizing block re-zeroes after reading (graph-replay safe)
__device__ float g_hist[NIMG * NBINS];
__device__ unsigned int g_count = 0;   // starts 0, reset to 0 each call

__device__ __forceinline__ float wscan(float x, int lane) {
    #pragma unroll
    for (int o = 1; o < 32; o <<= 1) {
        float n = __shfl_up_sync(0xffffffffu, x, o);
        if (lane >= o) x += n;
    }
    return x;
}

// ============================================================================
// R8 hist kernel (12.4us main phase) + fused warp-shuffle finalize.
// The FULL-unrolled 64-LDS reduce is deliberate register ballast: it forces a
// high allocation, keeping ptxas out of its 32-reg spill regime (R5-R7:
// every ~32-36-reg build spilled the hot loop, 28-45us). The fused finalize
// is shuffle-scan only (peak ~12 live floats, 24 regs standalone) so it
// cannot raise the kernel's register max past the 128-reg/4-blocks boundary
// -- unlike R3's fused finalize whose 64-LDS + 15-LDG unrolled batches forced
// 144 regs and cost a resident block.
// ============================================================================
__global__ __launch_bounds__(NT) void hist_kernel(const float* __restrict__ pred,
                                                  const float* __restrict__ tgt,
                                                  float* __restrict__ out) {
    // per-thread private histogram columns: sh[row*NT + tid]
    // bank = tid % 32 for every row -> conflict-free for any per-lane bin
    __shared__ float sh[NROW * NT];      // 36,864 B
    __shared__ float psum[2 * NBINS];
    __shared__ float accs[24];
    __shared__ bool  is_last;

    const int tid  = threadIdx.x;
    const int warp = tid >> 5;
    const int lane = tid & 31;
    const int img  = blockIdx.x / BPI;
    const int blk  = blockIdx.x % BPI;

    const float* src = (img < 24) ? pred : tgt;
    const int cimg   = (img < 24) ? img : img - 24;
    const float4* base = (const float4*)(src + (size_t)cimg * IMG_PIX);

    const int f0 = (blk    ) * IMG_F4 / BPI;
    const int f1 = (blk + 1) * IMG_F4 / BPI;

    for (int i = tid; i < NROW * NT; i += NT) sh[i] = 0.0f;
    __syncthreads();

    // Gaussian soft-assignment, geometric recurrence:
    // w_k = w0 * prod(s),  s: e^(+-C*d0)*v, then *= v^2 each step
    const float A   = 2048.0f;          // 1/(2*bin_width^2)
    const float DLT = 1.0f / 63.0f;
    const float C   = 4096.0f / 63.0f;  // 2*A*DLT
    const float v   = __expf(-A * DLT * DLT);
    const float v2  = v * v;

    for (int i = f0 + tid; i < f1; i += NT) {
        float4 xv = base[i];
        #pragma unroll
        for (int c = 0; c < 4; c++) {
            float x = (c == 0) ? xv.x : (c == 1) ? xv.y : (c == 2) ? xv.z : xv.w;
            // inputs uniform in [0,1): rn(x*63) already in [0,63]
            int j0 = __float2int_rn(x * 63.0f);
            float d0 = fmaf(-(float)j0, DLT, x);      // x - j0/63
            float w0 = __expf(-A * d0 * d0);
            float eu = __expf( C * d0);
            float ed = __expf(-C * d0);

            float* h = sh + (j0 + WIN) * NT + tid;    // immediate-offset RMWs
            h[0] += w0;

            float w = w0, s = eu * v;
            #pragma unroll
            for (int k = 1; k <= WIN; k++) {
                w *= s; s *= v2;
                h[k * NT] += w;
            }
            w = w0; s = ed * v;
            #pragma unroll
            for (int k = 1; k <= WIN; k++) {
                w *= s; s *= v2;
                h[-k * NT] += w;
            }
        }
    }
    __syncthreads();

    // Reduce 128 thread-columns. thread t: bin = t&63, half = t>>6 sums 64
    // cols. Lane-staggered start keeps banks distinct. FULL unroll on purpose
    // (register ballast; see header comment).
    {
        int bin  = tid & 63;
        int part = tid >> 6;
        int cbase = part * 64;
        const float* row = sh + (bin + WIN) * NT;
        float acc = 0.0f;
        #pragma unroll
        for (int i = 0; i < 64; i++) {
            acc += row[cbase + ((i + tid) & 63)];
        }
        psum[part * 64 + bin] = acc;
    }
    __syncthreads();
    if (tid < NBINS) {
        // spread-address atomics across 48*64 words: ~REDG rate, cheap.
        atomicAdd(&g_hist[img * NBINS + tid], psum[tid] + psum[64 + tid]);
    }

    // ---- last-block-done fused finalize (validated correct in R7) ----
    __threadfence();
    if (tid == 0) {
        unsigned int prev = atomicAdd(&g_count, 1u);
        is_last = (prev == NBLK - 1u);
    }
    __syncthreads();
    if (!is_last) return;

    // Only block still running; all atomics to g_hist are visible.
    // 4 warps x 6 channel pairs each; warp-shuffle cumsum over 64 bins.
    #pragma unroll 1
    for (int pair = warp; pair < 24; pair += 4) {
        const float* hp = g_hist + pair * NBINS;
        const float* ht = g_hist + (24 + pair) * NBINS;
        float pl = hp[lane], ph = hp[lane + 32];
        float tl = ht[lane], th = ht[lane + 32];

        float pls = wscan(pl, lane);
        float phs = wscan(ph, lane) + __shfl_sync(0xffffffffu, pls, 31);
        float tls = wscan(tl, lane);
        float ths = wscan(th, lane) + __shfl_sync(0xffffffffu, tls, 31);

        float rp = 1.0f / (__shfl_sync(0xffffffffu, phs, 31) + 1e-7f);
        float rt = 1.0f / (__shfl_sync(0xffffffffu, ths, 31) + 1e-7f);

        float acc = fabsf(pls * rp - tls * rt) + fabsf(phs * rp - ths * rt);
        #pragma unroll
        for (int o = 16; o > 0; o >>= 1)
            acc += __shfl_xor_sync(0xffffffffu, acc, o);
        if (lane == 0) accs[pair] = acc;
    }
    __syncthreads();

    if (tid == 0) {
        float s = 0.0f;
        #pragma unroll 1
        for (int c = 0; c < 24; c++) s += accs[c];
        out[0] = s * (1.0f / 1536.0f);   // mean over (8,3,64)
        g_count = 0;                     // reset for next replay
    }
    __syncthreads();
    // re-zero accumulators for the next replay (deterministic end state)
    #pragma unroll 1
    for (int p = tid; p < NIMG * NBINS; p += NT) g_hist[p] = 0.0f;
}

extern "C" void kernel_launch(void* const* d_in, const int* in_sizes, int n_in,
                              void* d_out, int out_size) {
    const float* pred = (const float*)d_in[0];
    const float* tgt  = (const float*)d_in[1];
    float* out        = (float*)d_out;

    hist_kernel<<<NBLK, NT>>>(pred, tgt, out);
}

// round 10
// speedup vs baseline: 1.2285x; 1.2285x over previous
#include <cuda_runtime.h>

#define NBINS 64
#define NT 128              // threads per block (hist kernel)
#define BPI 15              // blocks per image
#define NIMG 48             // 2 tensors * 8 batch * 3 channels
#define IMG_PIX 65536       // 256*256
#define IMG_F4 16384        // float4 elements per image
#define WIN 3               // half-width; tail ~4e-4 mass, cancels in cum-diff
#define NROW (NBINS + 2*WIN)  // 70 rows: bins -3..66 (guards absorb edges)
#define NBLK (NIMG * BPI)   // 720

// zero at load; finalize re-zeroes after reading each call (graph-replay safe)
__device__ float g_hist[NIMG * NBINS];

// ============================================================================
// R8 configuration EXACTLY (17.4us, the only fast compilation regime), with
// WIN=4 -> 3 as the single change. The main loop is at the smem-crossbar
// roofline (measured 12.4us vs 13us model), so fewer RMWs/pixel is the lever.
// The FULL-unrolled 64-LDS reduce is deliberate register ballast keeping
// ptxas out of its 32-40-reg spill regime (R5-R7, R9 evidence). DO NOT fuse
// the finalize into this kernel (R3/R7/R9: fusion always perturbed the
// allocation and doubled the main loop).
// ============================================================================
__global__ __launch_bounds__(NT) void hist_kernel(const float* __restrict__ pred,
                                                  const float* __restrict__ tgt) {
    // per-thread private histogram columns: sh[row*NT + tid]
    // bank = tid % 32 for every row -> conflict-free for any per-lane bin
    __shared__ float sh[NROW * NT];      // 35,840 B
    __shared__ float psum[2 * NBINS];

    const int tid = threadIdx.x;
    const int img = blockIdx.x / BPI;
    const int blk = blockIdx.x % BPI;

    const float* src = (img < 24) ? pred : tgt;
    const int cimg   = (img < 24) ? img : img - 24;
    const float4* base = (const float4*)(src + (size_t)cimg * IMG_PIX);

    const int f0 = (blk    ) * IMG_F4 / BPI;
    const int f1 = (blk + 1) * IMG_F4 / BPI;

    for (int i = tid; i < NROW * NT; i += NT) sh[i] = 0.0f;
    __syncthreads();

    // Gaussian soft-assignment, geometric recurrence:
    // w_k = w0 * prod(s),  s: e^(+-C*d0)*v, then *= v^2 each step
    const float A   = 2048.0f;          // 1/(2*bin_width^2)
    const float DLT = 1.0f / 63.0f;
    const float C   = 4096.0f / 63.0f;  // 2*A*DLT
    const float v   = __expf(-A * DLT * DLT);
    const float v2  = v * v;

    for (int i = f0 + tid; i < f1; i += NT) {
        float4 xv = base[i];
        #pragma unroll
        for (int c = 0; c < 4; c++) {
            float x = (c == 0) ? xv.x : (c == 1) ? xv.y : (c == 2) ? xv.z : xv.w;
            // inputs uniform in [0,1): rn(x*63) already in [0,63]
            int j0 = __float2int_rn(x * 63.0f);
            float d0 = fmaf(-(float)j0, DLT, x);      // x - j0/63
            float w0 = __expf(-A * d0 * d0);
            float eu = __expf( C * d0);
            float ed = __expf(-C * d0);

            float* h = sh + (j0 + WIN) * NT + tid;    // immediate-offset RMWs
            h[0] += w0;

            float w = w0, s = eu * v;
            #pragma unroll
            for (int k = 1; k <= WIN; k++) {
                w *= s; s *= v2;
                h[k * NT] += w;
            }
            w = w0; s = ed * v;
            #pragma unroll
            for (int k = 1; k <= WIN; k++) {
                w *= s; s *= v2;
                h[-k * NT] += w;
            }
        }
    }
    __syncthreads();

    // Reduce 128 thread-columns. thread t: bin = t&63, half = t>>6 sums 64
    // cols. Lane-staggered start keeps banks distinct. FULL unroll on purpose
    // (register ballast; see header comment).
    {
        int bin  = tid & 63;
        int part = tid >> 6;
        int cbase = part * 64;
        const float* row = sh + (bin + WIN) * NT;
        float acc = 0.0f;
        #pragma unroll
        for (int i = 0; i < 64; i++) {
            acc += row[cbase + ((i + tid) & 63)];
        }
        psum[part * 64 + bin] = acc;
    }
    __syncthreads();
    if (tid < NBINS) {
        // spread-address atomics across 48*64 words: ~REDG rate, cheap.
        atomicAdd(&g_hist[img * NBINS + tid], psum[tid] + psum[64 + tid]);
    }
}

// ============================================================================
// Finalize: 1 block x 768 threads = 24 warps, one (pred,target) channel pair
// per warp. Warp-shuffle inclusive cumsum over 64 bins, |diff| reduce, mean.
// Re-zeroes g_hist at the end so the next graph replay starts clean.
// ============================================================================
#define FNT 768

__device__ __forceinline__ float wscan(float x, int lane) {
    #pragma unroll
    for (int o = 1; o < 32; o <<= 1) {
        float n = __shfl_up_sync(0xffffffffu, x, o);
        if (lane >= o) x += n;
    }
    return x;
}

__global__ __launch_bounds__(FNT) void finalize_kernel(float* __restrict__ out) {
    __shared__ float accs[24];
    const int tid  = threadIdx.x;
    const int warp = tid >> 5;      // 0..23 = channel pair
    const int lane = tid & 31;

    const float* hp = g_hist + warp * NBINS;
    const float* ht = g_hist + (24 + warp) * NBINS;
    float pl = hp[lane], ph = hp[lane + 32];
    float tl = ht[lane], th = ht[lane + 32];

    float pls = wscan(pl, lane);
    float phs = wscan(ph, lane) + __shfl_sync(0xffffffffu, pls, 31);
    float tls = wscan(tl, lane);
    float ths = wscan(th, lane) + __shfl_sync(0xffffffffu, tls, 31);

    float rp = 1.0f / (__shfl_sync(0xffffffffu, phs, 31) + 1e-7f);
    float rt = 1.0f / (__shfl_sync(0xffffffffu, ths, 31) + 1e-7f);

    float acc = fabsf(pls * rp - tls * rt) + fabsf(phs * rp - ths * rt);
    #pragma unroll
    for (int o = 16; o > 0; o >>= 1)
        acc += __shfl_xor_sync(0xffffffffu, acc, o);
    if (lane == 0) accs[warp] = acc;
    __syncthreads();

    if (tid == 0) {
        float s = 0.0f;
        #pragma unroll
        for (int c = 0; c < 24; c++) s += accs[c];
        out[0] = s * (1.0f / 1536.0f);   // mean over (8,3,64)
    }

    // re-zero accumulators for the next replay (deterministic end state)
    for (int p = tid; p < NIMG * NBINS; p += FNT) g_hist[p] = 0.0f;
}

extern "C" void kernel_launch(void* const* d_in, const int* in_sizes, int n_in,
                              void* d_out, int out_size) {
    const float* pred = (const float*)d_in[0];
    const float* tgt  = (const float*)d_in[1];
    float* out        = (float*)d_out;

    hist_kernel<<<NBLK, NT>>>(pred, tgt);
    finalize_kernel<<<1, FNT>>>(out);
}

// round 11
// speedup vs baseline: 1.3898x; 1.1314x over previous
#include <cuda_runtime.h>

#define NBINS 64
#define NT 128              // threads per block (hist kernel)
#define BPI 12              // blocks per image -> NBLK 576 = 4*144: one wave
#define NIMG 48             // 2 tensors * 8 batch * 3 channels
#define IMG_PIX 65536       // 256*256
#define IMG_F4 16384        // float4 elements per image
#define WIN 3               // half-width (validated: rel_err 1.07e-4)
#define NROW (NBINS + 2*WIN)  // 70 rows: bins -3..66 (guards absorb edges)
#define NBLK (NIMG * BPI)   // 576

// zero at load; finalize re-zeroes after reading each call (graph-replay safe)
__device__ float g_hist[NIMG * NBINS];

// ============================================================================
// Hist kernel: byte-identical main loop to R8/R10 (the only fast compilation
// regime). FULL-unrolled 64-LDS reduce = register ballast keeping ptxas out
// of its 32-40-reg spill regime (R5-R7, R9). DO NOT fuse the finalize here
// (R3/R7/R9: fusion always perturbed allocation and doubled the main loop).
// R11 changes are compilation-neutral: BPI 15->12 (wave quantization),
// carveout attribute (runtime), PDL on finalize (launch overlap).
// ============================================================================
__global__ __launch_bounds__(NT) void hist_kernel(const float* __restrict__ pred,
                                                  const float* __restrict__ tgt) {
    // per-thread private histogram columns: sh[row*NT + tid]
    // bank = tid % 32 for every row -> conflict-free for any per-lane bin
    __shared__ float sh[NROW * NT];      // 35,840 B
    __shared__ float psum[2 * NBINS];

    const int tid = threadIdx.x;
    const int img = blockIdx.x / BPI;
    const int blk = blockIdx.x % BPI;

    const float* src = (img < 24) ? pred : tgt;
    const int cimg   = (img < 24) ? img : img - 24;
    const float4* base = (const float4*)(src + (size_t)cimg * IMG_PIX);

    const int f0 = (blk    ) * IMG_F4 / BPI;
    const int f1 = (blk + 1) * IMG_F4 / BPI;

    for (int i = tid; i < NROW * NT; i += NT) sh[i] = 0.0f;
    __syncthreads();

    // Gaussian soft-assignment, geometric recurrence:
    // w_k = w0 * prod(s),  s: e^(+-C*d0)*v, then *= v^2 each step
    const float A   = 2048.0f;          // 1/(2*bin_width^2)
    const float DLT = 1.0f / 63.0f;
    const float C   = 4096.0f / 63.0f;  // 2*A*DLT
    const float v   = __expf(-A * DLT * DLT);
    const float v2  = v * v;

    for (int i = f0 + tid; i < f1; i += NT) {
        float4 xv = base[i];
        #pragma unroll
        for (int c = 0; c < 4; c++) {
            float x = (c == 0) ? xv.x : (c == 1) ? xv.y : (c == 2) ? xv.z : xv.w;
            // inputs uniform in [0,1): rn(x*63) already in [0,63]
            int j0 = __float2int_rn(x * 63.0f);
            float d0 = fmaf(-(float)j0, DLT, x);      // x - j0/63
            float w0 = __expf(-A * d0 * d0);
            float eu = __expf( C * d0);
            float ed = __expf(-C * d0);

            float* h = sh + (j0 + WIN) * NT + tid;    // immediate-offset RMWs
            h[0] += w0;

            float w = w0, s = eu * v;
            #pragma unroll
            for (int k = 1; k <= WIN; k++) {
                w *= s; s *= v2;
                h[k * NT] += w;
            }
            w = w0; s = ed * v;
            #pragma unroll
            for (int k = 1; k <= WIN; k++) {
                w *= s; s *= v2;
                h[-k * NT] += w;
            }
        }
    }
    __syncthreads();

    // Reduce 128 thread-columns. thread t: bin = t&63, half = t>>6 sums 64
    // cols. Lane-staggered start keeps banks distinct. FULL unroll on purpose
    // (register ballast; see header comment).
    {
        int bin  = tid & 63;
        int part = tid >> 6;
        int cbase = part * 64;
        const float* row = sh + (bin + WIN) * NT;
        float acc = 0.0f;
        #pragma unroll
        for (int i = 0; i < 64; i++) {
            acc += row[cbase + ((i + tid) & 63)];
        }
        psum[part * 64 + bin] = acc;
    }
    __syncthreads();
    if (tid < NBINS) {
        // spread-address atomics across 48*64 words: ~REDG rate, cheap.
        atomicAdd(&g_hist[img * NBINS + tid], psum[tid] + psum[64 + tid]);
    }
}

// ============================================================================
// Finalize: 1 block x 768 threads = 24 warps, one (pred,target) channel pair
// per warp. Launched with PDL so its block is scheduled while hist runs; the
// cudaGridDependencySynchronize() gate releases when hist completes.
// Re-zeroes g_hist at the end so the next graph replay starts clean.
// ============================================================================
#define FNT 768

__device__ __forceinline__ float wscan(float x, int lane) {
    #pragma unroll
    for (int o = 1; o < 32; o <<= 1) {
        float n = __shfl_up_sync(0xffffffffu, x, o);
        if (lane >= o) x += n;
    }
    return x;
}

__global__ __launch_bounds__(FNT) void finalize_kernel(float* __restrict__ out) {
    // Wait for the preceding hist_kernel (PDL gate). All its atomics to
    // g_hist are visible after this returns.
    cudaGridDependencySynchronize();

    __shared__ float accs[24];
    const int tid  = threadIdx.x;
    const int warp = tid >> 5;      // 0..23 = channel pair
    const int lane = tid & 31;

    const float* hp = g_hist + warp * NBINS;
    const float* ht = g_hist + (24 + warp) * NBINS;
    float pl = hp[lane], ph = hp[lane + 32];
    float tl = ht[lane], th = ht[lane + 32];

    float pls = wscan(pl, lane);
    float phs = wscan(ph, lane) + __shfl_sync(0xffffffffu, pls, 31);
    float tls = wscan(tl, lane);
    float ths = wscan(th, lane) + __shfl_sync(0xffffffffu, tls, 31);

    float rp = 1.0f / (__shfl_sync(0xffffffffu, phs, 31) + 1e-7f);
    float rt = 1.0f / (__shfl_sync(0xffffffffu, ths, 31) + 1e-7f);

    float acc = fabsf(pls * rp - tls * rt) + fabsf(phs * rp - ths * rt);
    #pragma unroll
    for (int o = 16; o > 0; o >>= 1)
        acc += __shfl_xor_sync(0xffffffffu, acc, o);
    if (lane == 0) accs[warp] = acc;
    __syncthreads();

    if (tid == 0) {
        float s = 0.0f;
        #pragma unroll
        for (int c = 0; c < 24; c++) s += accs[c];
        out[0] = s * (1.0f / 1536.0f);   // mean over (8,3,64)
    }

    // re-zero accumulators for the next replay (deterministic end state)
    for (int p = tid; p < NIMG * NBINS; p += FNT) g_hist[p] = 0.0f;
}

extern "C" void kernel_launch(void* const* d_in, const int* in_sizes, int n_in,
                              void* d_out, int out_size) {
    const float* pred = (const float*)d_in[0];
    const float* tgt  = (const float*)d_in[1];
    float* out        = (float*)d_out;

    // Runtime attribute only (no codegen effect): allow 5-6 resident blocks
    // of 35.8KB if residency was carveout-limited at 4.
    cudaFuncSetAttribute(hist_kernel,
                         cudaFuncAttributePreferredSharedMemoryCarveout,
                         cudaSharedmemCarveoutMaxShared);

    hist_kernel<<<NBLK, NT>>>(pred, tgt);

    // PDL launch: finalize block is scheduled/prefetched while hist runs;
    // cudaGridDependencySynchronize() inside gates on hist completion.
    cudaLaunchConfig_t cfg = {};
    cfg.gridDim  = dim3(1, 1, 1);
    cfg.blockDim = dim3(FNT, 1, 1);
    cfg.dynamicSmemBytes = 0;
    cudaLaunchAttribute attrs[1];
    attrs[0].id = cudaLaunchAttributeProgrammaticStreamSerialization;
    attrs[0].val.programmaticStreamSerializationAllowed = 1;
    cfg.attrs = attrs;
    cfg.numAttrs = 1;
    cudaLaunchKernelEx(&cfg, finalize_kernel, out);
}